// round 11
// baseline (speedup 1.0000x reference)
#include <cuda_runtime.h>
#include <cstdint>

// B=256 batches of N=512 x 512 binary (0/1) float32 adjacency.
constexpr int B   = 256;
constexpr int N   = 512;
constexpr int W   = N / 32;    // 16 packed words per row
constexpr int F4  = N / 4;     // 128 float4 per row
constexpr int RPC1 = 32;       // rows per CTA, pack kernel
constexpr int GRID1 = B * (N / RPC1);  // 4096
constexpr int RPC2 = 64;       // rows per CTA, scale kernel
constexpr int GRID2 = B * (N / RPC2);  // 2048

// Scratch (__device__ globals: allocation-free rule).
// Transposed slot layout: word t lives at slot (t&3)*4 + (t>>2), so the uint4
// at slot-index g = words {g, 4+g, 8+g, 12+g} (exactly what K2 consumes).
__device__ unsigned g_bits[(size_t)B * N * W];  // 8 MB (L2-resident)
__device__ float    g_dis [(size_t)B * N];      // 512 KB

// Exact for 0.0/1.0 inputs: b = x0 + 2x1 + ... + 128x7  (<= 255, fp32-exact).
__device__ __forceinline__ unsigned byte8(const float4& a, const float4& b) {
    float f = a.x;
    f = fmaf(2.0f,   a.y, f);
    f = fmaf(4.0f,   a.z, f);
    f = fmaf(8.0f,   a.w, f);
    f = fmaf(16.0f,  b.x, f);
    f = fmaf(32.0f,  b.y, f);
    f = fmaf(64.0f,  b.z, f);
    f = fmaf(128.0f, b.w, f);
    return (unsigned)f;
}

// ---------------------------------------------------------------------------
// K1: pack + degree. Lane l owns bytes l and 32+l of each row bitmap.
// 4 LDG.128 per row; byte via FFMA; word via 2-step shfl-OR. 32 rows/CTA.
// ---------------------------------------------------------------------------
__global__ void __launch_bounds__(256)
pack_kernel(const float* __restrict__ adj) {
    const int bid   = blockIdx.x;
    const int batch = bid >> 4;
    const int r0    = (bid & 15) * RPC1;

    const int tid  = threadIdx.x;
    const int wid  = tid >> 5;
    const int lane = tid & 31;
    const int q4   = lane & 3;   // byte position within word
    const int wg   = lane >> 2;  // word-group 0..7

    const float4* a4 = reinterpret_cast<const float4*>(adj)
                     + ((size_t)batch * N + r0 + wid * 4) * F4;

    #pragma unroll
    for (int k = 0; k < 2; k++) {
        // Front-batch 2 rows = 8 independent LDG.128.
        float4 v[2][4];
        #pragma unroll
        for (int r = 0; r < 2; r++) {
            const float4* p = a4 + (size_t)(2 * k + r) * F4;
            v[r][0] = __ldcs(&p[2 * lane]);           // cols [8l,   8l+8)
            v[r][1] = __ldcs(&p[2 * lane + 1]);
            v[r][2] = __ldcs(&p[64 + 2 * lane]);      // cols [256+8l, ...)
            v[r][3] = __ldcs(&p[64 + 2 * lane + 1]);
        }

        #pragma unroll
        for (int r = 0; r < 2; r++) {
            // Byte l (half0) and byte 32+l (half1) of the 64-byte row bitmap.
            unsigned pw = byte8(v[r][0], v[r][1]) << (q4 * 8);
            unsigned qw = byte8(v[r][2], v[r][3]) << (q4 * 8);
            // 2-step OR-merge across the 4-lane word group.
            pw |= __shfl_xor_sync(0xffffffffu, pw, 1);
            qw |= __shfl_xor_sync(0xffffffffu, qw, 1);
            pw |= __shfl_xor_sync(0xffffffffu, pw, 2);
            qw |= __shfl_xor_sync(0xffffffffu, qw, 2);
            // Lane now holds word wg (pw, half0) and word 8+wg (qw, half1).

            int cnt = __popc(pw) + __popc(qw);
            cnt += __shfl_xor_sync(0xffffffffu, cnt, 4);
            cnt += __shfl_xor_sync(0xffffffffu, cnt, 8);
            cnt += __shfl_xor_sync(0xffffffffu, cnt, 16);  // full degree, all lanes

            const int ig = r0 + wid * 4 + 2 * k + r;       // row index within batch
            const int dw = ig >> 5, db = ig & 31;
            const unsigned diagw =
                __shfl_sync(0xffffffffu, (dw & 8) ? qw : pw, (dw & 7) * 4);
            const int diag = (diagw >> db) & 1;
            const int mask = (cnt != 0) ? 1 : 0;           // atom_mask
            const int deg  = cnt - diag + mask;            // degree_hat
            if (diag != mask && wg == (dw & 7)) {
                if (dw & 8) qw ^= (1u << db);
                else        pw ^= (1u << db);
            }

            // Transposed-slot store: word t -> slot (t&3)*4 + (t>>2).
            unsigned* gb = g_bits + ((size_t)batch * N + ig) * W;
            if (q4 == 0) gb[(wg & 3) * 4 + (wg >> 2)] = pw;            // t = wg
            if (q4 == 1) gb[((8 + wg) & 3) * 4 + ((8 + wg) >> 2)] = qw; // t = 8+wg
            if (lane == 0)
                g_dis[(size_t)batch * N + ig] = (deg > 0) ? rsqrtf((float)deg) : 0.0f;
        }
    }
}

// ---------------------------------------------------------------------------
// K2: out[i][j] = dis[i]*dis[j]*bit(i,j). Proven at the write cap — unchanged
// except REVERSED batch order (reads the L2-freshest bits first). PDL entry.
// ---------------------------------------------------------------------------
__global__ void __launch_bounds__(256)
scale_kernel(float* __restrict__ out) {
    const int bid   = blockIdx.x;
    const int batch = (B - 1) - (bid >> 3);   // reversed: hottest bits first
    const int r0    = (bid & 7) * RPC2;

    const int tid  = threadIdx.x;
    const int wid  = tid >> 5;
    const int lane = tid & 31;
    const int sub  = lane & 7;
    const int grp  = lane >> 3;

    const int lr = r0 + wid * 8;   // first of 8 rows for this warp (within batch)

    // PDL: wait until pack_kernel's writes are visible, then proceed.
    cudaGridDependencySynchronize();

    // Row-invariant column scales: dreg[c] = dis[c*128 + lane*4 .. +3].
    const float4* d4 = reinterpret_cast<const float4*>(g_dis + (size_t)batch * N);
    float4 dreg[4];
    #pragma unroll
    for (int c = 0; c < 4; c++) dreg[c] = __ldg(&d4[c * 32 + lane]);

    // Front-batch the 8 rows' packed words (one aligned uint4 per lane-group)
    // and the 8 row scales.
    const uint4* b4 = reinterpret_cast<const uint4*>(g_bits)
                    + ((size_t)batch * N + lr) * 4;
    uint4 wb[8];
    #pragma unroll
    for (int r = 0; r < 8; r++) wb[r] = __ldcg(&b4[(size_t)r * 4 + grp]);

    float di[8];
    #pragma unroll
    for (int r = 0; r < 8; r++) di[r] = __ldg(&g_dis[(size_t)batch * N + lr + r]);

    float4* o4 = reinterpret_cast<float4*>(out) + ((size_t)batch * N + lr) * F4;

    #pragma unroll
    for (int r = 0; r < 8; r++) {
        float4* q = o4 + (size_t)r * F4;
        const unsigned wc[4] = {wb[r].x, wb[r].y, wb[r].z, wb[r].w};  // word c*4+grp
        #pragma unroll
        for (int c = 0; c < 4; c++) {
            const unsigned nib = (wc[c] >> (sub * 4)) & 0xFu;
            const float4 d = dreg[c];
            float4 o;
            o.x = (nib & 1u) ? di[r] * d.x : 0.0f;
            o.y = (nib & 2u) ? di[r] * d.y : 0.0f;
            o.z = (nib & 4u) ? di[r] * d.z : 0.0f;
            o.w = (nib & 8u) ? di[r] * d.w : 0.0f;
            __stcs(&q[c * 32 + lane], o);  // coalesced STG.128 stream
        }
    }
}

extern "C" void kernel_launch(void* const* d_in, const int* in_sizes, int n_in,
                              void* d_out, int out_size) {
    const float* adj = (const float*)d_in[0];
    float* out = (float*)d_out;
    (void)in_sizes; (void)n_in; (void)out_size;

    pack_kernel<<<GRID1, 256>>>(adj);

    // PDL launch: K2 CTAs spin up during K1's tail wave; memory dependency is
    // enforced by cudaGridDependencySynchronize() in scale_kernel.
    cudaLaunchConfig_t cfg = {};
    cfg.gridDim  = dim3(GRID2);
    cfg.blockDim = dim3(256);
    cudaLaunchAttribute attr[1];
    attr[0].id = cudaLaunchAttributeProgrammaticStreamSerialization;
    attr[0].val.programmaticStreamSerializationAllowed = 1;
    cfg.attrs = attr;
    cfg.numAttrs = 1;
    cudaLaunchKernelEx(&cfg, scale_kernel, out);
}